// round 1
// baseline (speedup 1.0000x reference)
#include <cuda_runtime.h>

// Problem constants
#define B_    4096
#define N_    8
#define D_    256
#define FF_   2048
#define ROWS  (B_ * N_)      // 32768 layernorm rows
#define BD    (N_ * D_)      // 2048 flattened (n,d)

// ---------------- scratch (static device arrays; no allocation) ----------------
__device__ float g_xn[B_ * BD];           // LN1 output, (B, N*D)
__device__ float g_wfull[2][BD * BD];     // expanded circulant weights, Bt layout [c][k]
__device__ float g_x[B_ * BD];            // residual stream after TT product
__device__ float g_yn[B_ * BD];           // LN2 output
__device__ float g_h[(size_t)ROWS * FF_]; // FFN hidden (relu output)

// ---------------- packed fp32x2 FMA helpers ----------------
__device__ __forceinline__ void fma2(unsigned long long& acc, unsigned long long a,
                                     unsigned long long b) {
    asm("fma.rn.f32x2 %0, %1, %2, %0;" : "+l"(acc) : "l"(a), "l"(b));
}
__device__ __forceinline__ unsigned long long pack2(float x) {
    unsigned long long r;
    asm("mov.b64 %0, {%1, %1};" : "=l"(r) : "f"(x));
    return r;
}

// ---------------- layernorm: one warp per row of 256 ----------------
__global__ void ln_kernel(const float* __restrict__ in, const float* __restrict__ gamma,
                          const float* __restrict__ beta, float* __restrict__ out,
                          int rows) {
    int warp = (blockIdx.x * blockDim.x + threadIdx.x) >> 5;
    int lane = threadIdx.x & 31;
    if (warp >= rows) return;
    const float* r = in + (size_t)warp * D_;
    float v[8];
    float s = 0.f;
#pragma unroll
    for (int j = 0; j < 8; j++) { v[j] = r[j * 32 + lane]; s += v[j]; }
#pragma unroll
    for (int o = 16; o; o >>= 1) s += __shfl_xor_sync(0xffffffffu, s, o);
    float mu = s * (1.f / 256.f);
    float q = 0.f;
#pragma unroll
    for (int j = 0; j < 8; j++) { float d = v[j] - mu; q += d * d; }
#pragma unroll
    for (int o = 16; o; o >>= 1) q += __shfl_xor_sync(0xffffffffu, q, o);
    float inv = rsqrtf(q * (1.f / 256.f) + 1e-5f);
    float* w = out + (size_t)warp * D_;
#pragma unroll
    for (int j = 0; j < 8; j++) {
        int c = j * 32 + lane;
        w[c] = (v[j] - mu) * inv * gamma[c] + beta[c];
    }
}

// ---------------- expand circulant weights ----------------
// g_wfull[half][c*BD + kk] = w[d, o, (n-i)&7], c = n*256+o, kk = i*256+d
// w is (D, D, N) row-major: w[d][o][j] at ((d*256)+o)*8 + j
__global__ void expand_kernel(const float* __restrict__ w_in,
                              const float* __restrict__ w_out) {
    int idx = blockIdx.x * blockDim.x + threadIdx.x;   // 0 .. 2*BD*BD-1
    int half = idx >= BD * BD ? 1 : 0;
    int e = idx - half * (BD * BD);
    int c = e >> 11;        // / 2048
    int kk = e & 2047;
    int n = c >> 8, o = c & 255;
    int i = kk >> 8, d = kk & 255;
    int j = (n - i) & 7;
    const float* w = half ? w_out : w_in;
    g_wfull[half][(size_t)c * BD + kk] = w[(((d << 8) + o) << 3) + j];
}

// ---------------- SGEMM: C[m][n] = epi( A[m,:] . Bt[n,:] ) ----------------
// A: (M,K) row-major. Bt: (N,K) row-major (i.e. B transposed).
// flags: 1 = +bias[n], 2 = relu, 4 = +Add[m][n] (same layout as C)
#define F_BIAS 1
#define F_RELU 2
#define F_ADD  4

__global__ __launch_bounds__(256, 2) void sgemm_bt(
    const float* __restrict__ A, const float* __restrict__ Bt,
    const float* __restrict__ bias, const float* __restrict__ Add,
    float* __restrict__ C, int M, int N, int K, int flags) {
    __shared__ __align__(16) float As[8][128];
    __shared__ __align__(16) float Bs[8][128];
    const int tid = threadIdx.x;
    const int m0 = blockIdx.y * 128;
    const int n0 = blockIdx.x * 128;
    const int lrow = tid >> 1;            // 0..127
    const int lcol = (tid & 1) << 2;      // 0 or 4
    const int tx = tid & 15, ty = tid >> 4;

    unsigned long long acc2[8][4];
#pragma unroll
    for (int i = 0; i < 8; i++)
#pragma unroll
        for (int j = 0; j < 4; j++) acc2[i][j] = 0ULL;

    const float* Aptr = A + (size_t)(m0 + lrow) * K + lcol;
    const float* Bptr = Bt + (size_t)(n0 + lrow) * K + lcol;

    for (int k0 = 0; k0 < K; k0 += 8) {
        float4 av = *(const float4*)(Aptr + k0);
        float4 bv = *(const float4*)(Bptr + k0);
        As[lcol + 0][lrow] = av.x; As[lcol + 1][lrow] = av.y;
        As[lcol + 2][lrow] = av.z; As[lcol + 3][lrow] = av.w;
        Bs[lcol + 0][lrow] = bv.x; Bs[lcol + 1][lrow] = bv.y;
        Bs[lcol + 2][lrow] = bv.z; Bs[lcol + 3][lrow] = bv.w;
        __syncthreads();
#pragma unroll
        for (int kk = 0; kk < 8; kk++) {
            const float4 a0 = *(const float4*)&As[kk][ty * 8];
            const float4 a1 = *(const float4*)&As[kk][ty * 8 + 4];
            const ulonglong2 bb0 = *(const ulonglong2*)&Bs[kk][tx * 8];
            const ulonglong2 bb1 = *(const ulonglong2*)&Bs[kk][tx * 8 + 4];
            unsigned long long b2[4] = {bb0.x, bb0.y, bb1.x, bb1.y};
            float a[8] = {a0.x, a0.y, a0.z, a0.w, a1.x, a1.y, a1.z, a1.w};
#pragma unroll
            for (int i = 0; i < 8; i++) {
                unsigned long long a2 = pack2(a[i]);
#pragma unroll
                for (int j2 = 0; j2 < 4; j2++) fma2(acc2[i][j2], a2, b2[j2]);
            }
        }
        __syncthreads();
    }

#pragma unroll
    for (int i = 0; i < 8; i++) {
        int row = m0 + ty * 8 + i;
        size_t base = (size_t)row * N + n0 + tx * 8;
#pragma unroll
        for (int j2 = 0; j2 < 4; j2++) {
            unsigned long long v = acc2[i][j2];
            float lo = __uint_as_float((unsigned int)v);
            float hi = __uint_as_float((unsigned int)(v >> 32));
            int c0 = n0 + tx * 8 + j2 * 2;
            if (flags & F_BIAS) { lo += bias[c0]; hi += bias[c0 + 1]; }
            if (flags & F_RELU) { lo = fmaxf(lo, 0.f); hi = fmaxf(hi, 0.f); }
            if (flags & F_ADD)  { lo += Add[base + j2 * 2]; hi += Add[base + j2 * 2 + 1]; }
            C[base + j2 * 2]     = lo;
            C[base + j2 * 2 + 1] = hi;
        }
    }
}

// ---------------- host orchestration ----------------
extern "C" void kernel_launch(void* const* d_in, const int* in_sizes, int n_in,
                              void* d_out, int out_size) {
    (void)in_sizes; (void)n_in; (void)out_size;
    const float* ent  = (const float*)d_in[0];
    const float* w_in = (const float*)d_in[1];
    const float* w_out= (const float*)d_in[2];
    const float* W1   = (const float*)d_in[3];
    const float* b1   = (const float*)d_in[4];
    const float* W2   = (const float*)d_in[5];
    const float* b2   = (const float*)d_in[6];
    const float* g1   = (const float*)d_in[7];
    const float* be1  = (const float*)d_in[8];
    const float* g2   = (const float*)d_in[9];
    const float* be2  = (const float*)d_in[10];
    float* out = (float*)d_out;

    float *xn, *wf, *x, *yn, *h;
    cudaGetSymbolAddress((void**)&xn, g_xn);
    cudaGetSymbolAddress((void**)&wf, g_wfull);
    cudaGetSymbolAddress((void**)&x,  g_x);
    cudaGetSymbolAddress((void**)&yn, g_yn);
    cudaGetSymbolAddress((void**)&h,  g_h);

    // 1) LN1: xn = LN(ent_seq; gamma1, beta1)
    ln_kernel<<<ROWS / 8, 256>>>(ent, g1, be1, xn, ROWS);

    // 2) expand circulant weights into g_wfull
    expand_kernel<<<2 * BD * BD / 256, 256>>>(w_in, w_out);

    // 3) TT product as two 2048x2048x2048 GEMMs + residual
    //    x[b, c] = ent[b, c] + xn[b, :] . Wfull_t[c, :]
    sgemm_bt<<<dim3(BD / 128, (B_ / 2) / 128), 256>>>(
        xn, wf, nullptr, ent, x, B_ / 2, BD, BD, F_ADD);
    sgemm_bt<<<dim3(BD / 128, (B_ / 2) / 128), 256>>>(
        xn + (size_t)(B_ / 2) * BD, wf + (size_t)BD * BD, nullptr,
        ent + (size_t)(B_ / 2) * BD, x + (size_t)(B_ / 2) * BD,
        B_ / 2, BD, BD, F_ADD);

    // 4) LN2: yn = LN(x; gamma2, beta2)
    ln_kernel<<<ROWS / 8, 256>>>(x, g2, be2, yn, ROWS);

    // 5) FFN up: h = relu(yn @ W1^T + bias1)   (32768 x 2048 x 256)
    sgemm_bt<<<dim3(FF_ / 128, ROWS / 128), 256>>>(
        yn, W1, b1, nullptr, h, ROWS, FF_, D_, F_BIAS | F_RELU);

    // 6) FFN down + residual: out = x + h @ W2^T + bias2   (32768 x 256 x 2048)
    sgemm_bt<<<dim3(D_ / 128, ROWS / 128), 256>>>(
        h, W2, b2, x, out, ROWS, D_, FF_, F_BIAS | F_ADD);
}

// round 3
// speedup vs baseline: 3.5353x; 3.5353x over previous
#include <cuda_runtime.h>
#include <cstdint>

// Problem constants
#define B_    4096
#define N_    8
#define D_    256
#define FF_   2048
#define ROWS  (B_ * N_)      // 32768 layernorm rows
#define BD    (N_ * D_)      // 2048 flattened (n,d)

// ---------------- scratch (static device arrays; no allocation) ----------------
__device__ __align__(256) float g_xn[B_ * BD];           // LN1 output (tf32-rounded)
__device__ __align__(256) float g_wfull[2][BD * BD];     // expanded circulant weights [c][k]
__device__ __align__(256) float g_x[B_ * BD];            // residual stream after TT product
__device__ __align__(256) float g_yn[B_ * BD];           // LN2 output (tf32-rounded)
__device__ __align__(256) float g_h[(size_t)ROWS * FF_]; // FFN hidden (tf32-rounded)
__device__ __align__(256) float g_w1c[FF_ * D_];         // W1 tf32-rounded
__device__ __align__(256) float g_w2c[D_ * FF_];         // W2 tf32-rounded

// ---------------- helpers ----------------
__device__ __forceinline__ uint32_t smem_u32(const void* p) {
    uint32_t a;
    asm("{ .reg .u64 t; cvta.to.shared.u64 t, %1; cvt.u32.u64 %0, t; }" : "=r"(a) : "l"(p));
    return a;
}
__device__ __forceinline__ void cp16(uint32_t dst, const void* src) {
    asm volatile("cp.async.cg.shared.global [%0], [%1], 16;" :: "r"(dst), "l"(src));
}
__device__ __forceinline__ float tf32r(float x) {
    uint32_t r;
    asm("cvt.rna.tf32.f32 %0, %1;" : "=r"(r) : "f"(x));
    return __uint_as_float(r);
}
__device__ __forceinline__ void ldsm4(uint32_t& r0, uint32_t& r1, uint32_t& r2,
                                      uint32_t& r3, uint32_t addr) {
    asm volatile("ldmatrix.sync.aligned.m8n8.x4.shared.b16 {%0,%1,%2,%3}, [%4];"
                 : "=r"(r0), "=r"(r1), "=r"(r2), "=r"(r3) : "r"(addr));
}
__device__ __forceinline__ void mma_tf32(float& c0, float& c1, float& c2, float& c3,
                                         uint32_t a0, uint32_t a1, uint32_t a2, uint32_t a3,
                                         uint32_t b0, uint32_t b1) {
    asm volatile(
        "mma.sync.aligned.m16n8k8.row.col.f32.tf32.tf32.f32 "
        "{%0,%1,%2,%3}, {%4,%5,%6,%7}, {%8,%9}, {%0,%1,%2,%3};"
        : "+f"(c0), "+f"(c1), "+f"(c2), "+f"(c3)
        : "r"(a0), "r"(a1), "r"(a2), "r"(a3), "r"(b0), "r"(b1));
}

// ---------------- layernorm: one warp per row of 256; tf32-rounded output ----------------
__global__ void ln_kernel(const float* __restrict__ in, const float* __restrict__ gamma,
                          const float* __restrict__ beta, float* __restrict__ out,
                          int rows) {
    int warp = (blockIdx.x * blockDim.x + threadIdx.x) >> 5;
    int lane = threadIdx.x & 31;
    if (warp >= rows) return;
    const float* r = in + (size_t)warp * D_;
    float v[8];
    float s = 0.f;
#pragma unroll
    for (int j = 0; j < 8; j++) { v[j] = r[j * 32 + lane]; s += v[j]; }
#pragma unroll
    for (int o = 16; o; o >>= 1) s += __shfl_xor_sync(0xffffffffu, s, o);
    float mu = s * (1.f / 256.f);
    float q = 0.f;
#pragma unroll
    for (int j = 0; j < 8; j++) { float d = v[j] - mu; q += d * d; }
#pragma unroll
    for (int o = 16; o; o >>= 1) q += __shfl_xor_sync(0xffffffffu, q, o);
    float inv = rsqrtf(q * (1.f / 256.f) + 1e-5f);
    float* w = out + (size_t)warp * D_;
#pragma unroll
    for (int j = 0; j < 8; j++) {
        int c = j * 32 + lane;
        w[c] = tf32r((v[j] - mu) * inv * gamma[c] + beta[c]);
    }
}

// ---------------- expand circulant weights (tf32-rounded) ----------------
// g_wfull[half][c*BD + kk] = w[d, o, (n-i)&7], c = n*256+o, kk = i*256+d
__global__ void expand_kernel(const float* __restrict__ w_in,
                              const float* __restrict__ w_out) {
    int idx = blockIdx.x * blockDim.x + threadIdx.x;
    int half = idx >= BD * BD ? 1 : 0;
    int e = idx - half * (BD * BD);
    int c = e >> 11;
    int kk = e & 2047;
    int n = c >> 8, o = c & 255;
    int i = kk >> 8, d = kk & 255;
    int j = (n - i) & 7;
    const float* w = half ? w_out : w_in;
    g_wfull[half][(size_t)c * BD + kk] = tf32r(w[(((d << 8) + o) << 3) + j]);
}

// ---------------- tf32 round-copy for W1/W2 ----------------
__global__ void roundcopy_kernel(const float* __restrict__ a, float* __restrict__ b, int n) {
    int i = blockIdx.x * blockDim.x + threadIdx.x;
    if (i < n) b[i] = tf32r(a[i]);
}

// ---------------- tensor-core tf32 GEMM: C[m][n] = epi( A[m,:] . Bt[n,:] ) ----------------
// A: (M,K) row-major. Bt: (Ntot,K) row-major. 128x128 block tile, BK=32, 8 warps.
#define F_BIAS 1
#define F_RELU 2
#define F_ADD  4
#define F_TF32 8
#define STAGE_BYTES 32768          // A 16KB + B 16KB
#define SMEM_SZ (2 * STAGE_BYTES)  // double buffer

__global__ void __launch_bounds__(256, 2)
mm_kernel(const float* __restrict__ A, const float* __restrict__ Bt,
          const float* __restrict__ bias, const float* __restrict__ Add,
          float* __restrict__ C, int Ntot, int K, int flags) {
    extern __shared__ char sm[];
    const int tid = threadIdx.x, lid = tid & 31, wid = tid >> 5;
    const int wm = wid >> 2, wn = wid & 3;          // warp grid 2 x 4, warp tile 64x32
    const int m0 = blockIdx.y << 7, n0 = blockIdx.x << 7;
    const int nk = K >> 5;
    const uint32_t sbase = smem_u32(sm);

    // ---- loader mapping: thread t covers row t>>1 (0..127), chunk-half t&1 ----
    const int ldr = tid >> 1;
    const int ldh = tid & 1;
    const float* gA = A + (size_t)(m0 + ldr) * K + ldh * 16;
    const float* gB = Bt + (size_t)(n0 + ldr) * K + ldh * 16;
    const uint32_t swz = (uint32_t)(ldr & 7);

    // ---- fragment address constants ----
    const int r7 = lid & 7;
    const int rA = (lid & 7) + ((lid >> 3) & 1) * 8;  // A matrix row-in-16
    const int hA = lid >> 4;                          // A chunk half
    const int rB = (lid & 7) + (lid >> 4) * 8;        // B matrix row-in-16
    const int hB = (lid >> 3) & 1;                    // B chunk half

    float acc[4][4][4];
#pragma unroll
    for (int a = 0; a < 4; a++)
#pragma unroll
        for (int b = 0; b < 4; b++)
#pragma unroll
            for (int c = 0; c < 4; c++) acc[a][b][c] = 0.f;

#define LOAD_STAGE(buf, k0)                                                  \
    {                                                                        \
        uint32_t dA = sbase + (buf) * STAGE_BYTES + (uint32_t)ldr * 128;     \
        const float* pa = gA + (k0);                                         \
        const float* pb = gB + (k0);                                         \
        _Pragma("unroll")                                                    \
        for (int j = 0; j < 4; j++) {                                        \
            uint32_t c = (uint32_t)(ldh * 4 + j);                            \
            uint32_t so = (c ^ swz) << 4;                                    \
            cp16(dA + so, pa + j * 4);                                       \
            cp16(dA + 16384 + so, pb + j * 4);                               \
        }                                                                    \
        asm volatile("cp.async.commit_group;" ::: "memory");                 \
    }

    LOAD_STAGE(0, 0);

    for (int it = 0; it < nk; ++it) {
        const int cur = it & 1;
        if (it + 1 < nk) {
            LOAD_STAGE(cur ^ 1, (it + 1) * 32);
            asm volatile("cp.async.wait_group 1;" ::: "memory");
        } else {
            asm volatile("cp.async.wait_group 0;" ::: "memory");
        }
        __syncthreads();

        const uint32_t ab = sbase + cur * STAGE_BYTES;
        const uint32_t bb = ab + 16384;
#pragma unroll
        for (int kc = 0; kc < 4; kc++) {
            uint32_t af[4][4], bf[4][2];
#pragma unroll
            for (int mt = 0; mt < 4; mt++) {
                uint32_t row = (uint32_t)(wm * 64 + mt * 16 + rA);
                uint32_t ad = ab + row * 128 + ((((uint32_t)(kc * 2 + hA)) ^ (uint32_t)r7) << 4);
                ldsm4(af[mt][0], af[mt][1], af[mt][2], af[mt][3], ad);
            }
#pragma unroll
            for (int p = 0; p < 2; p++) {
                uint32_t row = (uint32_t)(wn * 32 + p * 16 + rB);
                uint32_t bd = bb + row * 128 + ((((uint32_t)(kc * 2 + hB)) ^ (uint32_t)r7) << 4);
                ldsm4(bf[2 * p][0], bf[2 * p][1], bf[2 * p + 1][0], bf[2 * p + 1][1], bd);
            }
#pragma unroll
            for (int mt = 0; mt < 4; mt++)
#pragma unroll
                for (int nt = 0; nt < 4; nt++)
                    mma_tf32(acc[mt][nt][0], acc[mt][nt][1], acc[mt][nt][2], acc[mt][nt][3],
                             af[mt][0], af[mt][1], af[mt][2], af[mt][3],
                             bf[nt][0], bf[nt][1]);
        }
        __syncthreads();
    }

    // ---- epilogue ----
    const int gid = lid >> 2, tig = lid & 3;
#pragma unroll
    for (int mt = 0; mt < 4; mt++) {
        const int row0 = m0 + wm * 64 + mt * 16 + gid;
#pragma unroll
        for (int nt = 0; nt < 4; nt++) {
            const int col = n0 + wn * 32 + nt * 8 + tig * 2;
            float v0 = acc[mt][nt][0], v1 = acc[mt][nt][1];
            float v2 = acc[mt][nt][2], v3 = acc[mt][nt][3];
            if (flags & F_BIAS) {
                float2 bv = *(const float2*)&bias[col];
                v0 += bv.x; v1 += bv.y; v2 += bv.x; v3 += bv.y;
            }
            if (flags & F_RELU) {
                v0 = fmaxf(v0, 0.f); v1 = fmaxf(v1, 0.f);
                v2 = fmaxf(v2, 0.f); v3 = fmaxf(v3, 0.f);
            }
            size_t i0 = (size_t)row0 * Ntot + col;
            size_t i1 = (size_t)(row0 + 8) * Ntot + col;
            if (flags & F_ADD) {
                float2 a0 = *(const float2*)&Add[i0];
                float2 a1 = *(const float2*)&Add[i1];
                v0 += a0.x; v1 += a0.y; v2 += a1.x; v3 += a1.y;
            }
            if (flags & F_TF32) {
                v0 = tf32r(v0); v1 = tf32r(v1); v2 = tf32r(v2); v3 = tf32r(v3);
            }
            float2 o0; o0.x = v0; o0.y = v1;
            float2 o1; o1.x = v2; o1.y = v3;
            *(float2*)&C[i0] = o0;
            *(float2*)&C[i1] = o1;
        }
    }
#undef LOAD_STAGE
}

// ---------------- host orchestration ----------------
extern "C" void kernel_launch(void* const* d_in, const int* in_sizes, int n_in,
                              void* d_out, int out_size) {
    (void)in_sizes; (void)n_in; (void)out_size;
    const float* ent  = (const float*)d_in[0];
    const float* w_in = (const float*)d_in[1];
    const float* w_out= (const float*)d_in[2];
    const float* W1   = (const float*)d_in[3];
    const float* b1   = (const float*)d_in[4];
    const float* W2   = (const float*)d_in[5];
    const float* b2   = (const float*)d_in[6];
    const float* g1   = (const float*)d_in[7];
    const float* be1  = (const float*)d_in[8];
    const float* g2   = (const float*)d_in[9];
    const float* be2  = (const float*)d_in[10];
    float* out = (float*)d_out;

    float *xn, *wf, *x, *yn, *h, *w1c, *w2c;
    cudaGetSymbolAddress((void**)&xn, g_xn);
    cudaGetSymbolAddress((void**)&wf, g_wfull);
    cudaGetSymbolAddress((void**)&x,  g_x);
    cudaGetSymbolAddress((void**)&yn, g_yn);
    cudaGetSymbolAddress((void**)&h,  g_h);
    cudaGetSymbolAddress((void**)&w1c, g_w1c);
    cudaGetSymbolAddress((void**)&w2c, g_w2c);

    cudaFuncSetAttribute(mm_kernel, cudaFuncAttributeMaxDynamicSharedMemorySize, SMEM_SZ);

    // 1) LN1 (tf32-rounded output)
    ln_kernel<<<ROWS / 8, 256>>>(ent, g1, be1, xn, ROWS);

    // 2) expand circulant weights + round W1/W2 copies
    expand_kernel<<<2 * BD * BD / 256, 256>>>(w_in, w_out);
    roundcopy_kernel<<<(FF_ * D_) / 256, 256>>>(W1, w1c, FF_ * D_);
    roundcopy_kernel<<<(D_ * FF_) / 256, 256>>>(W2, w2c, D_ * FF_);

    // 3) TT product: two (2048 x 2048 x 2048) GEMMs + residual
    mm_kernel<<<dim3(BD / 128, 16), 256, SMEM_SZ>>>(
        xn, wf, nullptr, ent, x, BD, BD, F_ADD);
    mm_kernel<<<dim3(BD / 128, 16), 256, SMEM_SZ>>>(
        xn + (size_t)(B_ / 2) * BD, wf + (size_t)BD * BD,
        nullptr, ent + (size_t)(B_ / 2) * BD, x + (size_t)(B_ / 2) * BD,
        BD, BD, F_ADD);

    // 4) LN2 (tf32-rounded output)
    ln_kernel<<<ROWS / 8, 256>>>(x, g2, be2, yn, ROWS);

    // 5) FFN up: h = relu(yn @ W1^T + b1)  (32768 x 2048 x 256), h rounded to tf32
    mm_kernel<<<dim3(FF_ / 128, ROWS / 128), 256, SMEM_SZ>>>(
        yn, w1c, b1, nullptr, h, FF_, D_, F_BIAS | F_RELU | F_TF32);

    // 6) FFN down + residual: out = x + h @ W2^T + b2  (32768 x 256 x 2048)
    mm_kernel<<<dim3(D_ / 128, ROWS / 128), 256, SMEM_SZ>>>(
        h, w2c, b2, x, out, D_, FF_, F_BIAS | F_ADD);
}

// round 4
// speedup vs baseline: 3.5424x; 1.0020x over previous
#include <cuda_runtime.h>
#include <cstdint>

// Problem constants
#define B_    4096
#define N_    8
#define D_    256
#define FF_   2048
#define ROWS  (B_ * N_)      // 32768 layernorm rows
#define BD    (N_ * D_)      // 2048 flattened (n,d)

// ---------------- scratch (static device arrays; no allocation) ----------------
__device__ __align__(256) float g_xn[B_ * BD];           // LN1 output (tf32-rounded)
__device__ __align__(256) float g_wfull[2][BD * BD];     // expanded circulant weights [c][k]
__device__ __align__(256) float g_x[B_ * BD];            // residual stream after TT product
__device__ __align__(256) float g_yn[B_ * BD];           // LN2 output (tf32-rounded)
__device__ __align__(256) float g_h[(size_t)ROWS * FF_]; // FFN hidden (tf32-rounded)
__device__ __align__(256) float g_w1c[FF_ * D_];         // W1 tf32-rounded
__device__ __align__(256) float g_w2c[D_ * FF_];         // W2 tf32-rounded

// ---------------- helpers ----------------
__device__ __forceinline__ uint32_t smem_u32(const void* p) {
    uint32_t a;
    asm("{ .reg .u64 t; cvta.to.shared.u64 t, %1; cvt.u32.u64 %0, t; }" : "=r"(a) : "l"(p));
    return a;
}
__device__ __forceinline__ void cp16(uint32_t dst, const void* src) {
    asm volatile("cp.async.cg.shared.global [%0], [%1], 16;" :: "r"(dst), "l"(src));
}
__device__ __forceinline__ float tf32r(float x) {
    uint32_t r;
    asm("cvt.rna.tf32.f32 %0, %1;" : "=r"(r) : "f"(x));
    return __uint_as_float(r);
}
__device__ __forceinline__ void ldsm4(uint32_t& r0, uint32_t& r1, uint32_t& r2,
                                      uint32_t& r3, uint32_t addr) {
    asm volatile("ldmatrix.sync.aligned.m8n8.x4.shared.b16 {%0,%1,%2,%3}, [%4];"
                 : "=r"(r0), "=r"(r1), "=r"(r2), "=r"(r3) : "r"(addr));
}
__device__ __forceinline__ void mma_tf32(float& c0, float& c1, float& c2, float& c3,
                                         uint32_t a0, uint32_t a1, uint32_t a2, uint32_t a3,
                                         uint32_t b0, uint32_t b1) {
    asm volatile(
        "mma.sync.aligned.m16n8k8.row.col.f32.tf32.tf32.f32 "
        "{%0,%1,%2,%3}, {%4,%5,%6,%7}, {%8,%9}, {%0,%1,%2,%3};"
        : "+f"(c0), "+f"(c1), "+f"(c2), "+f"(c3)
        : "r"(a0), "r"(a1), "r"(a2), "r"(a3), "r"(b0), "r"(b1));
}

// ---------------- layernorm: one warp per row of 256; tf32-rounded output ----------------
__global__ void ln_kernel(const float* __restrict__ in, const float* __restrict__ gamma,
                          const float* __restrict__ beta, float* __restrict__ out,
                          int rows) {
    int warp = (blockIdx.x * blockDim.x + threadIdx.x) >> 5;
    int lane = threadIdx.x & 31;
    if (warp >= rows) return;
    const float* r = in + (size_t)warp * D_;
    float v[8];
    float s = 0.f;
#pragma unroll
    for (int j = 0; j < 8; j++) { v[j] = r[j * 32 + lane]; s += v[j]; }
#pragma unroll
    for (int o = 16; o; o >>= 1) s += __shfl_xor_sync(0xffffffffu, s, o);
    float mu = s * (1.f / 256.f);
    float q = 0.f;
#pragma unroll
    for (int j = 0; j < 8; j++) { float d = v[j] - mu; q += d * d; }
#pragma unroll
    for (int o = 16; o; o >>= 1) q += __shfl_xor_sync(0xffffffffu, q, o);
    float inv = rsqrtf(q * (1.f / 256.f) + 1e-5f);
    float* w = out + (size_t)warp * D_;
#pragma unroll
    for (int j = 0; j < 8; j++) {
        int c = j * 32 + lane;
        w[c] = tf32r((v[j] - mu) * inv * gamma[c] + beta[c]);
    }
}

// ---------------- expand circulant weights (tf32-rounded) ----------------
// g_wfull[half][c*BD + kk] = w[d, o, (n-i)&7], c = n*256+o, kk = i*256+d
__global__ void expand_kernel(const float* __restrict__ w_in,
                              const float* __restrict__ w_out) {
    int idx = blockIdx.x * blockDim.x + threadIdx.x;
    int half = idx >= BD * BD ? 1 : 0;
    int e = idx - half * (BD * BD);
    int c = e >> 11;
    int kk = e & 2047;
    int n = c >> 8, o = c & 255;
    int i = kk >> 8, d = kk & 255;
    int j = (n - i) & 7;
    const float* w = half ? w_out : w_in;
    g_wfull[half][(size_t)c * BD + kk] = tf32r(w[(((d << 8) + o) << 3) + j]);
}

// ---------------- tf32 round-copy for W1/W2 ----------------
__global__ void roundcopy_kernel(const float* __restrict__ a, float* __restrict__ b, int n) {
    int i = blockIdx.x * blockDim.x + threadIdx.x;
    if (i < n) b[i] = tf32r(a[i]);
}

// ---------------- tensor-core tf32 GEMM: C[m][n] = epi( A[m,:] . Bt[n,:] ) ----------------
// A: (M,K) row-major. Bt: (Ntot,K) row-major. 128x128 block tile, BK=32, 8 warps.
#define F_BIAS 1
#define F_RELU 2
#define F_ADD  4
#define F_TF32 8
#define STAGE_BYTES 32768          // A 16KB + B 16KB
#define SMEM_SZ (2 * STAGE_BYTES)  // double buffer

__global__ void __launch_bounds__(256, 2)
mm_kernel(const float* __restrict__ A, const float* __restrict__ Bt,
          const float* __restrict__ bias, const float* __restrict__ Add,
          float* __restrict__ C, int Ntot, int K, int flags) {
    extern __shared__ char sm[];
    const int tid = threadIdx.x, lid = tid & 31, wid = tid >> 5;
    const int wm = wid >> 2, wn = wid & 3;          // warp grid 2 x 4, warp tile 64x32
    const int m0 = blockIdx.y << 7, n0 = blockIdx.x << 7;
    const int nk = K >> 5;
    const uint32_t sbase = smem_u32(sm);

    // ---- loader mapping: thread t covers row t>>1 (0..127), chunk-half t&1 ----
    const int ldr = tid >> 1;
    const int ldh = tid & 1;
    const float* gA = A + (size_t)(m0 + ldr) * K + ldh * 16;
    const float* gB = Bt + (size_t)(n0 + ldr) * K + ldh * 16;
    const uint32_t swz = (uint32_t)(ldr & 7);

    // ---- fragment address constants ----
    const int r7 = lid & 7;
    const int rA = (lid & 7) + ((lid >> 3) & 1) * 8;  // A matrix row-in-16
    const int hA = lid >> 4;                          // A chunk half
    const int rB = (lid & 7) + (lid >> 4) * 8;        // B matrix row-in-16
    const int hB = (lid >> 3) & 1;                    // B chunk half

    float acc[4][4][4];
#pragma unroll
    for (int a = 0; a < 4; a++)
#pragma unroll
        for (int b = 0; b < 4; b++)
#pragma unroll
            for (int c = 0; c < 4; c++) acc[a][b][c] = 0.f;

#define LOAD_STAGE(buf, k0)                                                  \
    {                                                                        \
        uint32_t dA = sbase + (buf) * STAGE_BYTES + (uint32_t)ldr * 128;     \
        const float* pa = gA + (k0);                                         \
        const float* pb = gB + (k0);                                         \
        _Pragma("unroll")                                                    \
        for (int j = 0; j < 4; j++) {                                        \
            uint32_t c = (uint32_t)(ldh * 4 + j);                            \
            uint32_t so = (c ^ swz) << 4;                                    \
            cp16(dA + so, pa + j * 4);                                       \
            cp16(dA + 16384 + so, pb + j * 4);                               \
        }                                                                    \
        asm volatile("cp.async.commit_group;" ::: "memory");                 \
    }

    LOAD_STAGE(0, 0);

    for (int it = 0; it < nk; ++it) {
        const int cur = it & 1;
        if (it + 1 < nk) {
            LOAD_STAGE(cur ^ 1, (it + 1) * 32);
            asm volatile("cp.async.wait_group 1;" ::: "memory");
        } else {
            asm volatile("cp.async.wait_group 0;" ::: "memory");
        }
        __syncthreads();

        const uint32_t ab = sbase + cur * STAGE_BYTES;
        const uint32_t bb = ab + 16384;
#pragma unroll
        for (int kc = 0; kc < 4; kc++) {
            uint32_t af[4][4], bf[4][2];
#pragma unroll
            for (int mt = 0; mt < 4; mt++) {
                uint32_t row = (uint32_t)(wm * 64 + mt * 16 + rA);
                uint32_t ad = ab + row * 128 + ((((uint32_t)(kc * 2 + hA)) ^ (uint32_t)r7) << 4);
                ldsm4(af[mt][0], af[mt][1], af[mt][2], af[mt][3], ad);
            }
#pragma unroll
            for (int p = 0; p < 2; p++) {
                uint32_t row = (uint32_t)(wn * 32 + p * 16 + rB);
                uint32_t bd = bb + row * 128 + ((((uint32_t)(kc * 2 + hB)) ^ (uint32_t)r7) << 4);
                ldsm4(bf[2 * p][0], bf[2 * p][1], bf[2 * p + 1][0], bf[2 * p + 1][1], bd);
            }
#pragma unroll
            for (int mt = 0; mt < 4; mt++)
#pragma unroll
                for (int nt = 0; nt < 4; nt++)
                    mma_tf32(acc[mt][nt][0], acc[mt][nt][1], acc[mt][nt][2], acc[mt][nt][3],
                             af[mt][0], af[mt][1], af[mt][2], af[mt][3],
                             bf[nt][0], bf[nt][1]);
        }
        __syncthreads();
    }

    // ---- epilogue ----
    const int gid = lid >> 2, tig = lid & 3;
#pragma unroll
    for (int mt = 0; mt < 4; mt++) {
        const int row0 = m0 + wm * 64 + mt * 16 + gid;
#pragma unroll
        for (int nt = 0; nt < 4; nt++) {
            const int col = n0 + wn * 32 + nt * 8 + tig * 2;
            float v0 = acc[mt][nt][0], v1 = acc[mt][nt][1];
            float v2 = acc[mt][nt][2], v3 = acc[mt][nt][3];
            if (flags & F_BIAS) {
                float2 bv = *(const float2*)&bias[col];
                v0 += bv.x; v1 += bv.y; v2 += bv.x; v3 += bv.y;
            }
            if (flags & F_RELU) {
                v0 = fmaxf(v0, 0.f); v1 = fmaxf(v1, 0.f);
                v2 = fmaxf(v2, 0.f); v3 = fmaxf(v3, 0.f);
            }
            size_t i0 = (size_t)row0 * Ntot + col;
            size_t i1 = (size_t)(row0 + 8) * Ntot + col;
            if (flags & F_ADD) {
                float2 a0 = *(const float2*)&Add[i0];
                float2 a1 = *(const float2*)&Add[i1];
                v0 += a0.x; v1 += a0.y; v2 += a1.x; v3 += a1.y;
            }
            if (flags & F_TF32) {
                v0 = tf32r(v0); v1 = tf32r(v1); v2 = tf32r(v2); v3 = tf32r(v3);
            }
            float2 o0; o0.x = v0; o0.y = v1;
            float2 o1; o1.x = v2; o1.y = v3;
            *(float2*)&C[i0] = o0;
            *(float2*)&C[i1] = o1;
        }
    }
#undef LOAD_STAGE
}

// ---------------- host orchestration ----------------
extern "C" void kernel_launch(void* const* d_in, const int* in_sizes, int n_in,
                              void* d_out, int out_size) {
    (void)in_sizes; (void)n_in; (void)out_size;
    const float* ent  = (const float*)d_in[0];
    const float* w_in = (const float*)d_in[1];
    const float* w_out= (const float*)d_in[2];
    const float* W1   = (const float*)d_in[3];
    const float* b1   = (const float*)d_in[4];
    const float* W2   = (const float*)d_in[5];
    const float* b2   = (const float*)d_in[6];
    const float* g1   = (const float*)d_in[7];
    const float* be1  = (const float*)d_in[8];
    const float* g2   = (const float*)d_in[9];
    const float* be2  = (const float*)d_in[10];
    float* out = (float*)d_out;

    float *xn, *wf, *x, *yn, *h, *w1c, *w2c;
    cudaGetSymbolAddress((void**)&xn, g_xn);
    cudaGetSymbolAddress((void**)&wf, g_wfull);
    cudaGetSymbolAddress((void**)&x,  g_x);
    cudaGetSymbolAddress((void**)&yn, g_yn);
    cudaGetSymbolAddress((void**)&h,  g_h);
    cudaGetSymbolAddress((void**)&w1c, g_w1c);
    cudaGetSymbolAddress((void**)&w2c, g_w2c);

    cudaFuncSetAttribute(mm_kernel, cudaFuncAttributeMaxDynamicSharedMemorySize, SMEM_SZ);

    // 1) LN1 (tf32-rounded output)
    ln_kernel<<<ROWS / 8, 256>>>(ent, g1, be1, xn, ROWS);

    // 2) expand circulant weights + round W1/W2 copies
    expand_kernel<<<2 * BD * BD / 256, 256>>>(w_in, w_out);
    roundcopy_kernel<<<(FF_ * D_) / 256, 256>>>(W1, w1c, FF_ * D_);
    roundcopy_kernel<<<(D_ * FF_) / 256, 256>>>(W2, w2c, D_ * FF_);

    // 3) TT product: two (2048 x 2048 x 2048) GEMMs + residual
    mm_kernel<<<dim3(BD / 128, 16), 256, SMEM_SZ>>>(
        xn, wf, nullptr, ent, x, BD, BD, F_ADD);
    mm_kernel<<<dim3(BD / 128, 16), 256, SMEM_SZ>>>(
        xn + (size_t)(B_ / 2) * BD, wf + (size_t)BD * BD,
        nullptr, ent + (size_t)(B_ / 2) * BD, x + (size_t)(B_ / 2) * BD,
        BD, BD, F_ADD);

    // 4) LN2 (tf32-rounded output)
    ln_kernel<<<ROWS / 8, 256>>>(x, g2, be2, yn, ROWS);

    // 5) FFN up: h = relu(yn @ W1^T + b1)  (32768 x 2048 x 256), h rounded to tf32
    mm_kernel<<<dim3(FF_ / 128, ROWS / 128), 256, SMEM_SZ>>>(
        yn, w1c, b1, nullptr, h, FF_, D_, F_BIAS | F_RELU | F_TF32);

    // 6) FFN down + residual: out = x + h @ W2^T + b2  (32768 x 256 x 2048)
    mm_kernel<<<dim3(D_ / 128, ROWS / 128), 256, SMEM_SZ>>>(
        h, w2c, b2, x, out, D_, FF_, F_BIAS | F_ADD);
}